// round 2
// baseline (speedup 1.0000x reference)
#include <cuda_runtime.h>

// Problem constants (fixed shapes per reference)
#define NSUM 6400
#define NMAX 64
#define MDIM 16
#define HDIM 32
#define ODIM 32
#define EDGES 51200

// Scratch: ping/pong node-feature buffers + CSR structures.
__device__ float g_h[2][NSUM * NMAX * HDIM];   // 2 x 52.4 MB
__device__ int g_cnt[NSUM];
__device__ int g_off[NSUM + 1];
__device__ int g_cur[NSUM];
__device__ int g_esrc[EDGES];

// ---------------------------------------------------------------------------
// CSR build: count -> exclusive scan -> scatter (bucket edges by dst)
// ---------------------------------------------------------------------------
__global__ void k_zero() {
    int i = blockIdx.x * blockDim.x + threadIdx.x;
    if (i < NSUM) g_cnt[i] = 0;
}

__global__ void k_count(const int* __restrict__ dst) {
    int e = blockIdx.x * blockDim.x + threadIdx.x;
    if (e < EDGES) atomicAdd(&g_cnt[dst[e]], 1);
}

__global__ void k_scan() {
    __shared__ int part[1024];
    int tid = threadIdx.x;
    const int CH = (NSUM + 1023) / 1024;  // 7
    int base = tid * CH;
    int s = 0;
    #pragma unroll
    for (int i = 0; i < CH; i++) {
        int idx = base + i;
        if (idx < NSUM) s += g_cnt[idx];
    }
    part[tid] = s;
    __syncthreads();
    int own = s;
    // Hillis-Steele inclusive scan over 1024 partials
    for (int d = 1; d < 1024; d <<= 1) {
        int v = (tid >= d) ? part[tid - d] : 0;
        __syncthreads();
        part[tid] += v;
        __syncthreads();
    }
    int run = part[tid] - own;  // exclusive prefix for this thread's chunk
    #pragma unroll
    for (int i = 0; i < CH; i++) {
        int idx = base + i;
        if (idx < NSUM) {
            g_off[idx] = run;
            g_cur[idx] = run;
            run += g_cnt[idx];
        }
    }
    if (tid == 1023) g_off[NSUM] = EDGES;
}

__global__ void k_scatter(const int* __restrict__ src, const int* __restrict__ dst) {
    int e = blockIdx.x * blockDim.x + threadIdx.x;
    if (e < EDGES) {
        int p = atomicAdd(&g_cur[dst[e]], 1);
        g_esrc[p] = src[e];
    }
}

// ---------------------------------------------------------------------------
// Fused GIN layer: agg (CSR gather-sum) + (1+eps)*h + 2-layer MLP (+pool)
// One block per node. 256 threads.
//   - aggregation: float4, linear element ownership, fully coalesced,
//     2-wide edge unroll for memory-level parallelism
//   - MLP: 4 threads per row; each thread produces 8 of the 32 outputs
//     (register accumulators; shared reads padded to be conflict-free)
//   - POOL (final layer): butterfly-shuffle row reduction + cross-warp smem
// ---------------------------------------------------------------------------
template <int DIN, bool RELU_OUT, bool POOL>
__global__ __launch_bounds__(256) void k_layer(
    const float* __restrict__ ext_in, int in_buf, int out_buf,
    const float* __restrict__ epsv, int layer,
    const float* __restrict__ W1, const float* __restrict__ b1,
    const float* __restrict__ W2, const float* __restrict__ b2,
    float* __restrict__ dout)
{
    constexpr int ELEMS = NMAX * DIN;        // 1024 (L0) or 2048
    constexpr int V4    = ELEMS / 4;          // float4 count per node
    constexpr int PT4   = V4 / 256;           // float4 per thread (1 or 2)
    constexpr int PADX  = DIN + 1;            // padded x row stride

    __shared__ float sW1[DIN * 32];
    __shared__ float sW2[32 * 32];
    __shared__ float sb1[32], sb2[32];
    __shared__ float sx[NMAX * PADX];
    __shared__ float shid[NMAX * 33];
    __shared__ int   sedge[128];

    int n = blockIdx.x;
    int tid = threadIdx.x;

    for (int i = tid; i < DIN * 32; i += 256) sW1[i] = W1[i];
    for (int i = tid; i < 32 * 32;  i += 256) sW2[i] = W2[i];
    if (tid < 32) { sb1[tid] = b1[tid]; sb2[tid] = b2[tid]; }
    float ep1 = 1.0f + epsv[layer];

    const float*  h_in = ext_in ? ext_in : g_h[in_buf];
    const float4* h4   = (const float4*)h_in;

    // ---- aggregation: acc = (1+eps)*h[n] + sum_{e in CSR[n]} h[src[e]] ----
    float4 acc[PT4];   // primary chain (starts with (1+eps)*h[n])
    float4 acc2[PT4];  // secondary chain (merged at the end)
    {
        const float4* hn = h4 + (size_t)n * V4;
        #pragma unroll
        for (int r = 0; r < PT4; r++) {
            float4 v = hn[tid + r * 256];
            acc[r]  = make_float4(ep1 * v.x, ep1 * v.y, ep1 * v.z, ep1 * v.w);
            acc2[r] = make_float4(0.0f, 0.0f, 0.0f, 0.0f);
        }
    }
    int e0 = g_off[n], e1 = g_off[n + 1];
    for (int eb = e0; eb < e1; eb += 128) {
        int nc = min(128, e1 - eb);
        __syncthreads();
        if (tid < nc) sedge[tid] = g_esrc[eb + tid];
        __syncthreads();
        int e = 0;
        for (; e + 2 <= nc; e += 2) {
            const float4* ha = h4 + (size_t)sedge[e]     * V4;
            const float4* hb = h4 + (size_t)sedge[e + 1] * V4;
            #pragma unroll
            for (int r = 0; r < PT4; r++) {
                float4 va = ha[tid + r * 256];
                float4 vb = hb[tid + r * 256];
                acc[r].x  += va.x; acc[r].y  += va.y;
                acc[r].z  += va.z; acc[r].w  += va.w;
                acc2[r].x += vb.x; acc2[r].y += vb.y;
                acc2[r].z += vb.z; acc2[r].w += vb.w;
            }
        }
        if (e < nc) {
            const float4* hs = h4 + (size_t)sedge[e] * V4;
            #pragma unroll
            for (int r = 0; r < PT4; r++) {
                float4 v = hs[tid + r * 256];
                acc[r].x += v.x; acc[r].y += v.y;
                acc[r].z += v.z; acc[r].w += v.w;
            }
        }
    }
    #pragma unroll
    for (int r = 0; r < PT4; r++) {
        acc[r].x += acc2[r].x; acc[r].y += acc2[r].y;
        acc[r].z += acc2[r].z; acc[r].w += acc2[r].w;
    }
    // store to padded shared x (float4 never crosses a row: 4 | DIN)
    #pragma unroll
    for (int r = 0; r < PT4; r++) {
        int idx = (tid + r * 256) * 4;
        int row = idx / DIN, col = idx % DIN;
        float* p = &sx[row * PADX + col];
        p[0] = acc[r].x; p[1] = acc[r].y; p[2] = acc[r].z; p[3] = acc[r].w;
    }
    __syncthreads();

    // ---- hidden: hid = relu(x @ W1 + b1) ----
    int row = tid >> 2, q = tid & 3;           // 4 threads per row, 8 j's each
    float hacc[8];
    #pragma unroll
    for (int i = 0; i < 8; i++) hacc[i] = sb1[q * 8 + i];
    #pragma unroll
    for (int k = 0; k < DIN; k++) {
        float xv = sx[row * PADX + k];
        #pragma unroll
        for (int i = 0; i < 8; i++)
            hacc[i] = fmaf(xv, sW1[k * 32 + q * 8 + i], hacc[i]);
    }
    #pragma unroll
    for (int i = 0; i < 8; i++)
        shid[row * 33 + q * 8 + i] = fmaxf(hacc[i], 0.0f);
    __syncthreads();

    // ---- output: out = hid @ W2 + b2 ----
    float oacc[8];
    #pragma unroll
    for (int i = 0; i < 8; i++) oacc[i] = sb2[q * 8 + i];
    #pragma unroll
    for (int j = 0; j < 32; j++) {
        float hv = shid[row * 33 + j];
        #pragma unroll
        for (int i = 0; i < 8; i++)
            oacc[i] = fmaf(hv, sW2[j * 32 + q * 8 + i], oacc[i]);
    }

    if (!POOL) {
        float* out = g_h[out_buf] + (size_t)n * (NMAX * 32) + row * 32 + q * 8;
        #pragma unroll
        for (int i = 0; i < 8; i++)
            out[i] = RELU_OUT ? fmaxf(oacc[i], 0.0f) : oacc[i];
    } else {
        // reduce over the 64 rows: shuffle over row bits within warp (8 rows),
        // then cross-warp via shared.
        #pragma unroll
        for (int s = 4; s <= 16; s <<= 1) {
            #pragma unroll
            for (int i = 0; i < 8; i++)
                oacc[i] += __shfl_xor_sync(0xffffffffu, oacc[i], s);
        }
        int lane = tid & 31, warp = tid >> 5;
        if (lane < 4) {
            #pragma unroll
            for (int i = 0; i < 8; i++)
                sx[warp * 32 + lane * 8 + i] = oacc[i];
        }
        __syncthreads();
        if (tid < 32) {
            float s = 0.0f;
            #pragma unroll
            for (int w = 0; w < 8; w++) s += sx[w * 32 + tid];
            dout[n * 32 + tid] = s;
        }
    }
}

// ---------------------------------------------------------------------------
extern "C" void kernel_launch(void* const* d_in, const int* in_sizes, int n_in,
                              void* d_out, int out_size)
{
    const float* W    = (const float*)d_in[0];   // [6400, 64, 16]
    const int*   ei   = (const int*)d_in[1];     // [2, E] row-major
    const float* eps  = (const float*)d_in[2];   // [3]
    const float* W1_0 = (const float*)d_in[3];
    const float* b1_0 = (const float*)d_in[4];
    const float* W2_0 = (const float*)d_in[5];
    const float* b2_0 = (const float*)d_in[6];
    const float* W1_1 = (const float*)d_in[7];
    const float* b1_1 = (const float*)d_in[8];
    const float* W2_1 = (const float*)d_in[9];
    const float* b2_1 = (const float*)d_in[10];
    const float* W1_2 = (const float*)d_in[11];
    const float* b1_2 = (const float*)d_in[12];
    const float* W2_2 = (const float*)d_in[13];
    const float* b2_2 = (const float*)d_in[14];
    float* out = (float*)d_out;

    const int* src = ei;
    const int* dst = ei + EDGES;

    // CSR build
    k_zero<<<(NSUM + 255) / 256, 256>>>();
    k_count<<<(EDGES + 255) / 256, 256>>>(dst);
    k_scan<<<1, 1024>>>();
    k_scatter<<<(EDGES + 255) / 256, 256>>>(src, dst);

    // Layer 0: input W (D=16) -> g_h[0]  (relu after MLP)
    k_layer<16, true, false><<<NSUM, 256>>>(W, 0, 0, eps, 0,
                                            W1_0, b1_0, W2_0, b2_0, nullptr);
    // Layer 1: g_h[0] -> g_h[1]  (relu after MLP)
    k_layer<32, true, false><<<NSUM, 256>>>(nullptr, 0, 1, eps, 1,
                                            W1_1, b1_1, W2_1, b2_1, nullptr);
    // Layer 2: g_h[1] -> pooled d_out  (no relu, sum over 64-row axis)
    k_layer<32, false, true><<<NSUM, 256>>>(nullptr, 1, 0, eps, 2,
                                            W1_2, b1_2, W2_2, b2_2, out);
}

// round 3
// speedup vs baseline: 1.0267x; 1.0267x over previous
#include <cuda_runtime.h>

// Problem constants (fixed shapes per reference)
#define NSUM 6400
#define NMAX 64
#define MDIM 16
#define HDIM 32
#define ODIM 32
#define EDGES 51200

// Scratch: ping/pong node-feature buffers + CSR structures + pool partials.
__device__ float g_h[2][NSUM * NMAX * HDIM];   // 2 x 52.4 MB
__device__ float g_pool[NSUM * 8 * 32];        // per-chunk pool partials
__device__ int g_cnt[NSUM];
__device__ int g_off[NSUM + 1];
__device__ int g_cur[NSUM];
__device__ int g_esrc[EDGES];

// ---------------------------------------------------------------------------
// CSR build: count -> exclusive scan -> scatter (bucket edges by dst)
// ---------------------------------------------------------------------------
__global__ void k_zero() {
    int i = blockIdx.x * blockDim.x + threadIdx.x;
    if (i < NSUM) g_cnt[i] = 0;
}

__global__ void k_count(const int* __restrict__ dst) {
    int e = blockIdx.x * blockDim.x + threadIdx.x;
    if (e < EDGES) atomicAdd(&g_cnt[dst[e]], 1);
}

__global__ void k_scan() {
    __shared__ int part[1024];
    int tid = threadIdx.x;
    const int CH = (NSUM + 1023) / 1024;  // 7
    int base = tid * CH;
    int s = 0;
    #pragma unroll
    for (int i = 0; i < CH; i++) {
        int idx = base + i;
        if (idx < NSUM) s += g_cnt[idx];
    }
    part[tid] = s;
    __syncthreads();
    int own = s;
    for (int d = 1; d < 1024; d <<= 1) {
        int v = (tid >= d) ? part[tid - d] : 0;
        __syncthreads();
        part[tid] += v;
        __syncthreads();
    }
    int run = part[tid] - own;
    #pragma unroll
    for (int i = 0; i < CH; i++) {
        int idx = base + i;
        if (idx < NSUM) {
            g_off[idx] = run;
            g_cur[idx] = run;
            run += g_cnt[idx];
        }
    }
    if (tid == 1023) g_off[NSUM] = EDGES;
}

__global__ void k_scatter(const int* __restrict__ src, const int* __restrict__ dst) {
    int e = blockIdx.x * blockDim.x + threadIdx.x;
    if (e < EDGES) {
        int p = atomicAdd(&g_cur[dst[e]], 1);
        g_esrc[p] = src[e];
    }
}

// ---------------------------------------------------------------------------
// Warp-autonomous fused GIN layer.
// Unit = (node, chunk of 8 rows). One warp per unit; grid-stride over units.
// Lane layout: lr = lane>>2 (row within chunk), q = lane&3 (col quarter).
//   gather : edge ids broadcast via shfl; thread loads its col-slice float4s
//   MLP    : x / hid staged in PER-WARP smem slices; only __syncwarp needed
//   weights: loaded to shared ONCE per block (persistent grid)
//   pool   : intra-warp row reduce + per-chunk partials; tiny reduce kernel
// ---------------------------------------------------------------------------
template <int DIN, bool RELU_OUT, bool POOL>
__global__ __launch_bounds__(256) void k_layer(
    const float* __restrict__ ext_in, int in_buf, int out_buf,
    const float* __restrict__ epsv, int layer,
    const float* __restrict__ W1, const float* __restrict__ b1,
    const float* __restrict__ W2, const float* __restrict__ b2)
{
    constexpr int V4   = NMAX * DIN / 4;   // float4 per node block
    constexpr int R4   = DIN / 4;          // float4 per row
    constexpr int NV   = DIN / 16;         // float4 per thread (1 or 2)
    constexpr int PADX = DIN + 4;          // padded x row stride (floats)
    constexpr int PADH = 36;               // padded hid row stride

    __shared__ float sW1[DIN * 32];
    __shared__ float sW2[32 * 32];
    __shared__ float sb1[32], sb2[32];
    __shared__ float sx[8][8 * PADX];      // per-warp x slices
    __shared__ float sh[8][8 * PADH];      // per-warp hid slices

    int tid = threadIdx.x;
    int wid = tid >> 5, lane = tid & 31;
    int lr = lane >> 2, q = lane & 3;

    for (int i = tid; i < DIN * 32; i += 256) sW1[i] = W1[i];
    for (int i = tid; i < 32 * 32;  i += 256) sW2[i] = W2[i];
    if (tid < 32) { sb1[tid] = b1[tid]; sb2[tid] = b2[tid]; }
    float ep1 = 1.0f + epsv[layer];
    __syncthreads();

    const float*  h_in = ext_in ? ext_in : g_h[in_buf];
    const float4* h4   = (const float4*)h_in;
    float* sxw = sx[wid];
    float* shw = sh[wid];

    for (int unit = blockIdx.x * 8 + wid; unit < NSUM * 8; unit += gridDim.x * 8) {
        int n = unit >> 3, chunk = unit & 7;
        int grow = chunk * 8 + lr;                 // global row in [0,64)
        int roff = grow * R4;                      // float4 offset of row

        // ---- gather: acc = (1+eps)*h[n] + sum_neighbors h[src] ----
        float4 a0[NV], a1[NV];
        {
            const float4* hn = h4 + (size_t)n * V4 + roff;
            #pragma unroll
            for (int v = 0; v < NV; v++) {
                float4 t = hn[q + v * 4];
                a0[v] = make_float4(ep1 * t.x, ep1 * t.y, ep1 * t.z, ep1 * t.w);
                a1[v] = make_float4(0.f, 0.f, 0.f, 0.f);
            }
        }
        int e0 = g_off[n], e1 = g_off[n + 1];
        for (int base = e0; base < e1; base += 32) {
            int cnt = min(32, e1 - base);
            int id = (lane < cnt) ? g_esrc[base + lane] : 0;
            int e = 0;
            for (; e + 2 <= cnt; e += 2) {
                int sa = __shfl_sync(0xffffffffu, id, e);
                int sb = __shfl_sync(0xffffffffu, id, e + 1);
                const float4* pa = h4 + (size_t)sa * V4 + roff;
                const float4* pb = h4 + (size_t)sb * V4 + roff;
                #pragma unroll
                for (int v = 0; v < NV; v++) {
                    float4 ta = pa[q + v * 4];
                    float4 tb = pb[q + v * 4];
                    a0[v].x += ta.x; a0[v].y += ta.y; a0[v].z += ta.z; a0[v].w += ta.w;
                    a1[v].x += tb.x; a1[v].y += tb.y; a1[v].z += tb.z; a1[v].w += tb.w;
                }
            }
            if (e < cnt) {
                int sa = __shfl_sync(0xffffffffu, id, e);
                const float4* pa = h4 + (size_t)sa * V4 + roff;
                #pragma unroll
                for (int v = 0; v < NV; v++) {
                    float4 ta = pa[q + v * 4];
                    a0[v].x += ta.x; a0[v].y += ta.y; a0[v].z += ta.z; a0[v].w += ta.w;
                }
            }
        }
        // stage x into this warp's smem slice; thread's float4 v covers
        // float cols 4q + 16v .. +3 of row lr.
        #pragma unroll
        for (int v = 0; v < NV; v++) {
            float s0 = a0[v].x + a1[v].x, s1 = a0[v].y + a1[v].y;
            float s2 = a0[v].z + a1[v].z, s3 = a0[v].w + a1[v].w;
            float* p = &sxw[lr * PADX + 4 * q + 16 * v];
            p[0] = s0; p[1] = s1; p[2] = s2; p[3] = s3;
        }
        __syncwarp();

        // ---- hidden: hid = relu(x @ W1 + b1); thread owns cols q*8..+8 ----
        float hacc[8];
        #pragma unroll
        for (int i = 0; i < 8; i++) hacc[i] = sb1[q * 8 + i];
        #pragma unroll
        for (int k = 0; k < DIN; k++) {
            float xv = sxw[lr * PADX + k];
            #pragma unroll
            for (int i = 0; i < 8; i++)
                hacc[i] = fmaf(xv, sW1[k * 32 + q * 8 + i], hacc[i]);
        }
        {
            float* p = &shw[lr * PADH + q * 8];
            #pragma unroll
            for (int i = 0; i < 8; i++) p[i] = fmaxf(hacc[i], 0.0f);
        }
        __syncwarp();

        // ---- output: out = hid @ W2 + b2 ----
        float oacc[8];
        #pragma unroll
        for (int i = 0; i < 8; i++) oacc[i] = sb2[q * 8 + i];
        #pragma unroll
        for (int j = 0; j < 32; j++) {
            float hv = shw[lr * PADH + j];
            #pragma unroll
            for (int i = 0; i < 8; i++)
                oacc[i] = fmaf(hv, sW2[j * 32 + q * 8 + i], oacc[i]);
        }
        __syncwarp();   // reads done before next iteration's stage writes

        if (!POOL) {
            float* out = g_h[out_buf] + (size_t)n * (NMAX * 32) + grow * 32 + q * 8;
            float4 o0 = make_float4(oacc[0], oacc[1], oacc[2], oacc[3]);
            float4 o1 = make_float4(oacc[4], oacc[5], oacc[6], oacc[7]);
            if (RELU_OUT) {
                o0.x = fmaxf(o0.x, 0.f); o0.y = fmaxf(o0.y, 0.f);
                o0.z = fmaxf(o0.z, 0.f); o0.w = fmaxf(o0.w, 0.f);
                o1.x = fmaxf(o1.x, 0.f); o1.y = fmaxf(o1.y, 0.f);
                o1.z = fmaxf(o1.z, 0.f); o1.w = fmaxf(o1.w, 0.f);
            }
            ((float4*)out)[0] = o0;
            ((float4*)out)[1] = o1;
        } else {
            // sum over the warp's 8 rows (lr bits = lane bits 2,3,4)
            #pragma unroll
            for (int s = 4; s <= 16; s <<= 1) {
                #pragma unroll
                for (int i = 0; i < 8; i++)
                    oacc[i] += __shfl_xor_sync(0xffffffffu, oacc[i], s);
            }
            if (lane < 4) {
                float* p = &g_pool[n * 256 + chunk * 32 + q * 8];
                ((float4*)p)[0] = make_float4(oacc[0], oacc[1], oacc[2], oacc[3]);
                ((float4*)p)[1] = make_float4(oacc[4], oacc[5], oacc[6], oacc[7]);
            }
        }
    }
}

// Reduce the 8 per-chunk partials into the final [NSUM, 32] output.
__global__ void k_pool_reduce(float* __restrict__ dout) {
    int i = blockIdx.x * blockDim.x + threadIdx.x;   // i = n*32 + c
    if (i < NSUM * 32) {
        int n = i >> 5, c = i & 31;
        const float* p = &g_pool[n * 256 + c];
        float s = 0.0f;
        #pragma unroll
        for (int ch = 0; ch < 8; ch++) s += p[ch * 32];
        dout[i] = s;
    }
}

// ---------------------------------------------------------------------------
extern "C" void kernel_launch(void* const* d_in, const int* in_sizes, int n_in,
                              void* d_out, int out_size)
{
    const float* W    = (const float*)d_in[0];   // [6400, 64, 16]
    const int*   ei   = (const int*)d_in[1];     // [2, E] row-major
    const float* eps  = (const float*)d_in[2];   // [3]
    const float* W1_0 = (const float*)d_in[3];
    const float* b1_0 = (const float*)d_in[4];
    const float* W2_0 = (const float*)d_in[5];
    const float* b2_0 = (const float*)d_in[6];
    const float* W1_1 = (const float*)d_in[7];
    const float* b1_1 = (const float*)d_in[8];
    const float* W2_1 = (const float*)d_in[9];
    const float* b2_1 = (const float*)d_in[10];
    const float* W1_2 = (const float*)d_in[11];
    const float* b1_2 = (const float*)d_in[12];
    const float* W2_2 = (const float*)d_in[13];
    const float* b2_2 = (const float*)d_in[14];
    float* out = (float*)d_out;

    const int* src = ei;
    const int* dst = ei + EDGES;

    // CSR build
    k_zero<<<(NSUM + 255) / 256, 256>>>();
    k_count<<<(EDGES + 255) / 256, 256>>>(dst);
    k_scan<<<1, 1024>>>();
    k_scatter<<<(EDGES + 255) / 256, 256>>>(src, dst);

    const int GRID = 592;   // 148 SMs x 4 resident blocks

    // Layer 0: input W (D=16) -> g_h[0]  (relu after MLP)
    k_layer<16, true, false><<<GRID, 256>>>(W, 0, 0, eps, 0,
                                            W1_0, b1_0, W2_0, b2_0);
    // Layer 1: g_h[0] -> g_h[1]  (relu after MLP)
    k_layer<32, true, false><<<GRID, 256>>>(nullptr, 0, 1, eps, 1,
                                            W1_1, b1_1, W2_1, b2_1);
    // Layer 2: g_h[1] -> per-chunk pool partials (no relu)
    k_layer<32, false, true><<<GRID, 256>>>(nullptr, 1, 0, eps, 2,
                                            W1_2, b1_2, W2_2, b2_2);
    // Final: reduce 8 chunk partials per node
    k_pool_reduce<<<(NSUM * 32 + 255) / 256, 256>>>(out);
}

// round 4
// speedup vs baseline: 1.5388x; 1.4987x over previous
#include <cuda_runtime.h>

// Problem constants (fixed shapes per reference)
#define NSUM 6400
#define NMAX 64
#define MDIM 16
#define HDIM 32
#define ODIM 32
#define EDGES 51200

// Scratch: ping/pong node-feature buffers + CSR structures + pool partials.
__device__ float g_h[2][NSUM * NMAX * HDIM];   // 2 x 52.4 MB
__device__ float g_pool[NSUM * 2 * 32];        // per-half pool partials
__device__ int g_cnt[NSUM];
__device__ int g_off[NSUM + 1];
__device__ int g_cur[NSUM];
__device__ int g_esrc[EDGES];

// ---------------------------------------------------------------------------
// CSR build: count -> exclusive scan -> scatter (bucket edges by dst)
// ---------------------------------------------------------------------------
__global__ void k_zero() {
    int i = blockIdx.x * blockDim.x + threadIdx.x;
    if (i < NSUM) g_cnt[i] = 0;
}

__global__ void k_count(const int* __restrict__ dst) {
    int e = blockIdx.x * blockDim.x + threadIdx.x;
    if (e < EDGES) atomicAdd(&g_cnt[dst[e]], 1);
}

__global__ void k_scan() {
    __shared__ int part[1024];
    int tid = threadIdx.x;
    const int CH = (NSUM + 1023) / 1024;  // 7
    int base = tid * CH;
    int s = 0;
    #pragma unroll
    for (int i = 0; i < CH; i++) {
        int idx = base + i;
        if (idx < NSUM) s += g_cnt[idx];
    }
    part[tid] = s;
    __syncthreads();
    int own = s;
    for (int d = 1; d < 1024; d <<= 1) {
        int v = (tid >= d) ? part[tid - d] : 0;
        __syncthreads();
        part[tid] += v;
        __syncthreads();
    }
    int run = part[tid] - own;
    #pragma unroll
    for (int i = 0; i < CH; i++) {
        int idx = base + i;
        if (idx < NSUM) {
            g_off[idx] = run;
            g_cur[idx] = run;
            run += g_cnt[idx];
        }
    }
    if (tid == 1023) g_off[NSUM] = EDGES;
}

__global__ void k_scatter(const int* __restrict__ src, const int* __restrict__ dst) {
    int e = blockIdx.x * blockDim.x + threadIdx.x;
    if (e < EDGES) {
        int p = atomicAdd(&g_cur[dst[e]], 1);
        g_esrc[p] = src[e];
    }
}

// ---------------------------------------------------------------------------
// Warp-autonomous fused GIN layer, high-FFMA-density mapping.
// Unit = (node, half of 32 rows). One warp per unit; grid-stride over units.
// Lane (lr = lane>>2, q = lane&3) owns 4 rows {lr, lr+8, lr+16, lr+24} of
// its half, and 8 output columns [q*8, q*8+8).
//   gather : edge ids broadcast via shfl; per edge each lane issues
//            4*PFR independent LDG.128 (rows x col-slices)
//   MLP    : x staged in per-warp smem (stride 36, conflict-free);
//            per k-step: 4 x-LDS + 2 weight-LDS.128 + 32 FFMA.
//            hid overwrites the x buffer after a __syncwarp (smem union).
//   weights: loaded to shared once per block (persistent-ish grid)
//   pool   : local 4-row sum + shfl over lr bits; 2 partials/node + reduce
// ---------------------------------------------------------------------------
template <int DIN, bool RELU_OUT, bool POOL>
__global__ __launch_bounds__(256) void k_layer(
    const float* __restrict__ ext_in, int in_buf, int out_buf,
    const float* __restrict__ epsv, int layer,
    const float* __restrict__ W1, const float* __restrict__ b1,
    const float* __restrict__ W2, const float* __restrict__ b2)
{
    constexpr int R4   = DIN / 4;          // float4 per row
    constexpr int PFR  = R4 / 4;           // float4 per lane per row (1 or 2)
    constexpr int V4   = NMAX * R4;        // float4 per node block
    constexpr int PAD  = 36;               // row stride in union buffer

    __shared__ float sW1[DIN * 32];
    __shared__ float sW2[32 * 32];
    __shared__ float sb1[32], sb2[32];
    __shared__ float sxh[8][32 * PAD];     // per-warp x/hid union slices

    int tid = threadIdx.x;
    int wid = tid >> 5, lane = tid & 31;
    int lr = lane >> 2, q = lane & 3;

    for (int i = tid; i < DIN * 32; i += 256) sW1[i] = W1[i];
    for (int i = tid; i < 32 * 32;  i += 256) sW2[i] = W2[i];
    if (tid < 32) { sb1[tid] = b1[tid]; sb2[tid] = b2[tid]; }
    float ep1 = 1.0f + epsv[layer];
    __syncthreads();

    const float*  h_in = ext_in ? ext_in : g_h[in_buf];
    const float4* h4   = (const float4*)h_in;
    float* sxw = sxh[wid];

    for (int unit = blockIdx.x * 8 + wid; unit < NSUM * 2; unit += gridDim.x * 8) {
        int n = unit >> 1, half = unit & 1;
        // lane's float4 slots within the node block (4 rows x PFR slices)
        int slot[4 * PFR];
        #pragma unroll
        for (int m = 0; m < 4; m++)
            #pragma unroll
            for (int v = 0; v < PFR; v++)
                slot[m * PFR + v] = (half * 32 + lr + 8 * m) * R4 + q + 4 * v;

        // ---- gather: acc = (1+eps)*h[n] + sum_neighbors h[src] ----
        float4 acc[4 * PFR];
        {
            const float4* hn = h4 + (size_t)n * V4;
            #pragma unroll
            for (int s = 0; s < 4 * PFR; s++) {
                float4 t = hn[slot[s]];
                acc[s] = make_float4(ep1 * t.x, ep1 * t.y, ep1 * t.z, ep1 * t.w);
            }
        }
        int e0 = g_off[n], e1 = g_off[n + 1];
        for (int base = e0; base < e1; base += 32) {
            int cnt = min(32, e1 - base);
            int id = (lane < cnt) ? g_esrc[base + lane] : 0;
            for (int e = 0; e < cnt; e++) {
                int sa = __shfl_sync(0xffffffffu, id, e);
                const float4* pa = h4 + (size_t)sa * V4;
                #pragma unroll
                for (int s = 0; s < 4 * PFR; s++) {
                    float4 t = pa[slot[s]];
                    acc[s].x += t.x; acc[s].y += t.y;
                    acc[s].z += t.z; acc[s].w += t.w;
                }
            }
        }
        // stage x into this warp's smem slice (local rows lr+8m)
        #pragma unroll
        for (int m = 0; m < 4; m++)
            #pragma unroll
            for (int v = 0; v < PFR; v++) {
                float4 t = acc[m * PFR + v];
                float* p = &sxw[(lr + 8 * m) * PAD + 4 * q + 16 * v];
                p[0] = t.x; p[1] = t.y; p[2] = t.z; p[3] = t.w;
            }
        __syncwarp();

        // ---- hidden: hid = relu(x @ W1 + b1); lane: 4 rows x 8 cols ----
        float hacc[32];
        #pragma unroll
        for (int m = 0; m < 4; m++)
            #pragma unroll
            for (int i = 0; i < 8; i++) hacc[m * 8 + i] = sb1[q * 8 + i];
        #pragma unroll
        for (int k = 0; k < DIN; k++) {
            float xv0 = sxw[(lr +  0) * PAD + k];
            float xv1 = sxw[(lr +  8) * PAD + k];
            float xv2 = sxw[(lr + 16) * PAD + k];
            float xv3 = sxw[(lr + 24) * PAD + k];
            #pragma unroll
            for (int i = 0; i < 8; i++) {
                float w = sW1[k * 32 + q * 8 + i];
                hacc[ 0 + i] = fmaf(xv0, w, hacc[ 0 + i]);
                hacc[ 8 + i] = fmaf(xv1, w, hacc[ 8 + i]);
                hacc[16 + i] = fmaf(xv2, w, hacc[16 + i]);
                hacc[24 + i] = fmaf(xv3, w, hacc[24 + i]);
            }
        }
        __syncwarp();   // all x reads done before hid overwrites the buffer
        #pragma unroll
        for (int m = 0; m < 4; m++) {
            float* p = &sxw[(lr + 8 * m) * PAD + q * 8];
            #pragma unroll
            for (int i = 0; i < 8; i++) p[i] = fmaxf(hacc[m * 8 + i], 0.0f);
        }
        __syncwarp();

        // ---- output: out = hid @ W2 + b2 ----
        float oacc[32];
        #pragma unroll
        for (int m = 0; m < 4; m++)
            #pragma unroll
            for (int i = 0; i < 8; i++) oacc[m * 8 + i] = sb2[q * 8 + i];
        #pragma unroll
        for (int j = 0; j < 32; j++) {
            float h0 = sxw[(lr +  0) * PAD + j];
            float h1 = sxw[(lr +  8) * PAD + j];
            float h2 = sxw[(lr + 16) * PAD + j];
            float h3 = sxw[(lr + 24) * PAD + j];
            #pragma unroll
            for (int i = 0; i < 8; i++) {
                float w = sW2[j * 32 + q * 8 + i];
                oacc[ 0 + i] = fmaf(h0, w, oacc[ 0 + i]);
                oacc[ 8 + i] = fmaf(h1, w, oacc[ 8 + i]);
                oacc[16 + i] = fmaf(h2, w, oacc[16 + i]);
                oacc[24 + i] = fmaf(h3, w, oacc[24 + i]);
            }
        }
        __syncwarp();   // hid reads done before next iteration stages x

        if (!POOL) {
            #pragma unroll
            for (int m = 0; m < 4; m++) {
                int grow = half * 32 + lr + 8 * m;
                float* out = g_h[out_buf] + (size_t)n * (NMAX * 32) + grow * 32 + q * 8;
                float4 o0 = make_float4(oacc[m*8+0], oacc[m*8+1], oacc[m*8+2], oacc[m*8+3]);
                float4 o1 = make_float4(oacc[m*8+4], oacc[m*8+5], oacc[m*8+6], oacc[m*8+7]);
                if (RELU_OUT) {
                    o0.x = fmaxf(o0.x, 0.f); o0.y = fmaxf(o0.y, 0.f);
                    o0.z = fmaxf(o0.z, 0.f); o0.w = fmaxf(o0.w, 0.f);
                    o1.x = fmaxf(o1.x, 0.f); o1.y = fmaxf(o1.y, 0.f);
                    o1.z = fmaxf(o1.z, 0.f); o1.w = fmaxf(o1.w, 0.f);
                }
                ((float4*)out)[0] = o0;
                ((float4*)out)[1] = o1;
            }
        } else {
            // local sum over this lane's 4 rows
            float o[8];
            #pragma unroll
            for (int i = 0; i < 8; i++)
                o[i] = oacc[i] + oacc[8 + i] + oacc[16 + i] + oacc[24 + i];
            // reduce over lr (lane bits 2..4)
            #pragma unroll
            for (int s = 4; s <= 16; s <<= 1) {
                #pragma unroll
                for (int i = 0; i < 8; i++)
                    o[i] += __shfl_xor_sync(0xffffffffu, o[i], s);
            }
            if (lane < 4) {
                float* p = &g_pool[n * 64 + half * 32 + q * 8];
                ((float4*)p)[0] = make_float4(o[0], o[1], o[2], o[3]);
                ((float4*)p)[1] = make_float4(o[4], o[5], o[6], o[7]);
            }
        }
    }
}

// Reduce the 2 per-half partials into the final [NSUM, 32] output.
__global__ void k_pool_reduce(float* __restrict__ dout) {
    int i = blockIdx.x * blockDim.x + threadIdx.x;   // i = n*32 + c
    if (i < NSUM * 32) {
        int n = i >> 5, c = i & 31;
        dout[i] = g_pool[n * 64 + c] + g_pool[n * 64 + 32 + c];
    }
}

// ---------------------------------------------------------------------------
extern "C" void kernel_launch(void* const* d_in, const int* in_sizes, int n_in,
                              void* d_out, int out_size)
{
    const float* W    = (const float*)d_in[0];   // [6400, 64, 16]
    const int*   ei   = (const int*)d_in[1];     // [2, E] row-major
    const float* eps  = (const float*)d_in[2];   // [3]
    const float* W1_0 = (const float*)d_in[3];
    const float* b1_0 = (const float*)d_in[4];
    const float* W2_0 = (const float*)d_in[5];
    const float* b2_0 = (const float*)d_in[6];
    const float* W1_1 = (const float*)d_in[7];
    const float* b1_1 = (const float*)d_in[8];
    const float* W2_1 = (const float*)d_in[9];
    const float* b2_1 = (const float*)d_in[10];
    const float* W1_2 = (const float*)d_in[11];
    const float* b1_2 = (const float*)d_in[12];
    const float* W2_2 = (const float*)d_in[13];
    const float* b2_2 = (const float*)d_in[14];
    float* out = (float*)d_out;

    const int* src = ei;
    const int* dst = ei + EDGES;

    // CSR build
    k_zero<<<(NSUM + 255) / 256, 256>>>();
    k_count<<<(EDGES + 255) / 256, 256>>>(dst);
    k_scan<<<1, 1024>>>();
    k_scatter<<<(EDGES + 255) / 256, 256>>>(src, dst);

    const int GRID = 592;

    // Layer 0: input W (D=16) -> g_h[0]  (relu after MLP)
    k_layer<16, true, false><<<GRID, 256>>>(W, 0, 0, eps, 0,
                                            W1_0, b1_0, W2_0, b2_0);
    // Layer 1: g_h[0] -> g_h[1]  (relu after MLP)
    k_layer<32, true, false><<<GRID, 256>>>(nullptr, 0, 1, eps, 1,
                                            W1_1, b1_1, W2_1, b2_1);
    // Layer 2: g_h[1] -> per-half pool partials (no relu)
    k_layer<32, false, true><<<GRID, 256>>>(nullptr, 1, 0, eps, 2,
                                            W1_2, b1_2, W2_2, b2_2);
    // Final: reduce 2 half partials per node
    k_pool_reduce<<<(NSUM * 32 + 255) / 256, 256>>>(out);
}

// round 5
// speedup vs baseline: 1.8335x; 1.1915x over previous
#include <cuda_runtime.h>

// Problem constants (fixed shapes per reference)
#define NSUM 6400
#define NMAX 64
#define MDIM 16
#define HDIM 32
#define ODIM 32
#define EDGES 51200

// Scratch: ping/pong node-feature buffers + CSR structures + pool partials.
__device__ float g_h[2][NSUM * NMAX * HDIM];   // 2 x 52.4 MB
__device__ float g_pool[NSUM * 2 * 32];        // per-half pool partials
__device__ int g_cnt[NSUM];                    // zero-init at load; k_scan re-zeroes
__device__ int g_off[NSUM + 1];
__device__ int g_cur[NSUM];
__device__ int g_esrc[EDGES];

// ---------------------------------------------------------------------------
// CSR build: count -> scan (self-cleaning) -> scatter
// g_cnt starts zeroed (static init); k_scan zeroes it again after consuming,
// so every graph replay sees a clean counter array. This drops the k_zero
// launch so the heavy layer-0 kernel sits at launch index 3 (ncu -s window).
// ---------------------------------------------------------------------------
__global__ void k_count(const int* __restrict__ dst) {
    int e = blockIdx.x * blockDim.x + threadIdx.x;
    if (e < EDGES) atomicAdd(&g_cnt[dst[e]], 1);
}

__global__ void k_scan() {
    __shared__ int part[1024];
    int tid = threadIdx.x;
    const int CH = (NSUM + 1023) / 1024;  // 7
    int base = tid * CH;
    int s = 0;
    #pragma unroll
    for (int i = 0; i < CH; i++) {
        int idx = base + i;
        if (idx < NSUM) s += g_cnt[idx];
    }
    part[tid] = s;
    __syncthreads();
    int own = s;
    for (int d = 1; d < 1024; d <<= 1) {
        int v = (tid >= d) ? part[tid - d] : 0;
        __syncthreads();
        part[tid] += v;
        __syncthreads();
    }
    int run = part[tid] - own;
    #pragma unroll
    for (int i = 0; i < CH; i++) {
        int idx = base + i;
        if (idx < NSUM) {
            g_off[idx] = run;
            g_cur[idx] = run;
            run += g_cnt[idx];
            g_cnt[idx] = 0;          // self-clean for the next replay
        }
    }
    if (tid == 1023) g_off[NSUM] = EDGES;
}

__global__ void k_scatter(const int* __restrict__ src, const int* __restrict__ dst) {
    int e = blockIdx.x * blockDim.x + threadIdx.x;
    if (e < EDGES) {
        int p = atomicAdd(&g_cur[dst[e]], 1);
        g_esrc[p] = src[e];
    }
}

// ---------------------------------------------------------------------------
// Warp-autonomous fused GIN layer, high-FFMA-density mapping.
// Unit = (node, half of 32 rows). One warp per unit; grid-stride over units.
// Lane (lr = lane>>2, q = lane&3) owns 4 rows {lr, lr+8, lr+16, lr+24} of
// its half, and 8 output columns [q*8, q*8+8).
//   gather : edge ids broadcast via shfl; 2-edge-wide register-buffered
//            loads (16 LDG.128 in flight) to hide L2 latency
//   MLP    : x staged in per-warp smem (stride 36, conflict-free);
//            per k-step: 4 x-LDS + 2 weight-LDS.128 + 32 FFMA.
//            hid overwrites the x buffer after a __syncwarp (smem union).
//   weights: loaded to shared once per block (persistent grid)
//   pool   : local 4-row sum + shfl over lr bits; 2 partials/node + reduce
// ---------------------------------------------------------------------------
template <int DIN, bool RELU_OUT, bool POOL>
__global__ __launch_bounds__(256, 2) void k_layer(
    const float* __restrict__ ext_in, int in_buf, int out_buf,
    const float* __restrict__ epsv, int layer,
    const float* __restrict__ W1, const float* __restrict__ b1,
    const float* __restrict__ W2, const float* __restrict__ b2)
{
    constexpr int R4   = DIN / 4;          // float4 per row
    constexpr int PFR  = R4 / 4;           // float4 per lane per row (1 or 2)
    constexpr int S    = 4 * PFR;          // float4 slots per lane (4 or 8)
    constexpr int V4   = NMAX * R4;        // float4 per node block
    constexpr int PAD  = 36;               // row stride in union buffer

    __shared__ float sW1[DIN * 32];
    __shared__ float sW2[32 * 32];
    __shared__ float sb1[32], sb2[32];
    __shared__ float sxh[8][32 * PAD];     // per-warp x/hid union slices

    int tid = threadIdx.x;
    int wid = tid >> 5, lane = tid & 31;
    int lr = lane >> 2, q = lane & 3;

    for (int i = tid; i < DIN * 32; i += 256) sW1[i] = W1[i];
    for (int i = tid; i < 32 * 32;  i += 256) sW2[i] = W2[i];
    if (tid < 32) { sb1[tid] = b1[tid]; sb2[tid] = b2[tid]; }
    float ep1 = 1.0f + epsv[layer];
    __syncthreads();

    const float*  h_in = ext_in ? ext_in : g_h[in_buf];
    const float4* h4   = (const float4*)h_in;
    float* sxw = sxh[wid];

    for (int unit = blockIdx.x * 8 + wid; unit < NSUM * 2; unit += gridDim.x * 8) {
        int n = unit >> 1, half = unit & 1;
        // lane's float4 slots within the node block (4 rows x PFR slices)
        int slot[S];
        #pragma unroll
        for (int m = 0; m < 4; m++)
            #pragma unroll
            for (int v = 0; v < PFR; v++)
                slot[m * PFR + v] = (half * 32 + lr + 8 * m) * R4 + q + 4 * v;

        // ---- gather: acc = (1+eps)*h[n] + sum_neighbors h[src] ----
        float4 acc[S];
        {
            const float4* hn = h4 + (size_t)n * V4;
            #pragma unroll
            for (int s = 0; s < S; s++) {
                float4 t = hn[slot[s]];
                acc[s] = make_float4(ep1 * t.x, ep1 * t.y, ep1 * t.z, ep1 * t.w);
            }
        }
        int e0 = g_off[n], e1 = g_off[n + 1];
        for (int base = e0; base < e1; base += 32) {
            int cnt = min(32, e1 - base);
            int id = (lane < cnt) ? g_esrc[base + lane] : 0;
            int e = 0;
            for (; e + 2 <= cnt; e += 2) {
                int sa = __shfl_sync(0xffffffffu, id, e);
                int sb = __shfl_sync(0xffffffffu, id, e + 1);
                const float4* pa = h4 + (size_t)sa * V4;
                const float4* pb = h4 + (size_t)sb * V4;
                float4 ta[S], tb[S];
                #pragma unroll
                for (int s = 0; s < S; s++) ta[s] = pa[slot[s]];
                #pragma unroll
                for (int s = 0; s < S; s++) tb[s] = pb[slot[s]];
                #pragma unroll
                for (int s = 0; s < S; s++) {
                    acc[s].x += ta[s].x; acc[s].y += ta[s].y;
                    acc[s].z += ta[s].z; acc[s].w += ta[s].w;
                }
                #pragma unroll
                for (int s = 0; s < S; s++) {
                    acc[s].x += tb[s].x; acc[s].y += tb[s].y;
                    acc[s].z += tb[s].z; acc[s].w += tb[s].w;
                }
            }
            if (e < cnt) {
                int sa = __shfl_sync(0xffffffffu, id, e);
                const float4* pa = h4 + (size_t)sa * V4;
                #pragma unroll
                for (int s = 0; s < S; s++) {
                    float4 t = pa[slot[s]];
                    acc[s].x += t.x; acc[s].y += t.y;
                    acc[s].z += t.z; acc[s].w += t.w;
                }
            }
        }
        // stage x into this warp's smem slice (local rows lr+8m)
        #pragma unroll
        for (int m = 0; m < 4; m++)
            #pragma unroll
            for (int v = 0; v < PFR; v++) {
                float4 t = acc[m * PFR + v];
                float* p = &sxw[(lr + 8 * m) * PAD + 4 * q + 16 * v];
                p[0] = t.x; p[1] = t.y; p[2] = t.z; p[3] = t.w;
            }
        __syncwarp();

        // ---- hidden: hid = relu(x @ W1 + b1); lane: 4 rows x 8 cols ----
        float hacc[32];
        #pragma unroll
        for (int m = 0; m < 4; m++)
            #pragma unroll
            for (int i = 0; i < 8; i++) hacc[m * 8 + i] = sb1[q * 8 + i];
        #pragma unroll
        for (int k = 0; k < DIN; k++) {
            float xv0 = sxw[(lr +  0) * PAD + k];
            float xv1 = sxw[(lr +  8) * PAD + k];
            float xv2 = sxw[(lr + 16) * PAD + k];
            float xv3 = sxw[(lr + 24) * PAD + k];
            #pragma unroll
            for (int i = 0; i < 8; i++) {
                float w = sW1[k * 32 + q * 8 + i];
                hacc[ 0 + i] = fmaf(xv0, w, hacc[ 0 + i]);
                hacc[ 8 + i] = fmaf(xv1, w, hacc[ 8 + i]);
                hacc[16 + i] = fmaf(xv2, w, hacc[16 + i]);
                hacc[24 + i] = fmaf(xv3, w, hacc[24 + i]);
            }
        }
        __syncwarp();   // all x reads done before hid overwrites the buffer
        #pragma unroll
        for (int m = 0; m < 4; m++) {
            float* p = &sxw[(lr + 8 * m) * PAD + q * 8];
            #pragma unroll
            for (int i = 0; i < 8; i++) p[i] = fmaxf(hacc[m * 8 + i], 0.0f);
        }
        __syncwarp();

        // ---- output: out = hid @ W2 + b2 ----
        float oacc[32];
        #pragma unroll
        for (int m = 0; m < 4; m++)
            #pragma unroll
            for (int i = 0; i < 8; i++) oacc[m * 8 + i] = sb2[q * 8 + i];
        #pragma unroll
        for (int j = 0; j < 32; j++) {
            float h0 = sxw[(lr +  0) * PAD + j];
            float h1 = sxw[(lr +  8) * PAD + j];
            float h2 = sxw[(lr + 16) * PAD + j];
            float h3 = sxw[(lr + 24) * PAD + j];
            #pragma unroll
            for (int i = 0; i < 8; i++) {
                float w = sW2[j * 32 + q * 8 + i];
                oacc[ 0 + i] = fmaf(h0, w, oacc[ 0 + i]);
                oacc[ 8 + i] = fmaf(h1, w, oacc[ 8 + i]);
                oacc[16 + i] = fmaf(h2, w, oacc[16 + i]);
                oacc[24 + i] = fmaf(h3, w, oacc[24 + i]);
            }
        }
        __syncwarp();   // hid reads done before next iteration stages x

        if (!POOL) {
            #pragma unroll
            for (int m = 0; m < 4; m++) {
                int grow = half * 32 + lr + 8 * m;
                float* out = g_h[out_buf] + (size_t)n * (NMAX * 32) + grow * 32 + q * 8;
                float4 o0 = make_float4(oacc[m*8+0], oacc[m*8+1], oacc[m*8+2], oacc[m*8+3]);
                float4 o1 = make_float4(oacc[m*8+4], oacc[m*8+5], oacc[m*8+6], oacc[m*8+7]);
                if (RELU_OUT) {
                    o0.x = fmaxf(o0.x, 0.f); o0.y = fmaxf(o0.y, 0.f);
                    o0.z = fmaxf(o0.z, 0.f); o0.w = fmaxf(o0.w, 0.f);
                    o1.x = fmaxf(o1.x, 0.f); o1.y = fmaxf(o1.y, 0.f);
                    o1.z = fmaxf(o1.z, 0.f); o1.w = fmaxf(o1.w, 0.f);
                }
                ((float4*)out)[0] = o0;
                ((float4*)out)[1] = o1;
            }
        } else {
            // local sum over this lane's 4 rows
            float o[8];
            #pragma unroll
            for (int i = 0; i < 8; i++)
                o[i] = oacc[i] + oacc[8 + i] + oacc[16 + i] + oacc[24 + i];
            // reduce over lr (lane bits 2..4)
            #pragma unroll
            for (int s = 4; s <= 16; s <<= 1) {
                #pragma unroll
                for (int i = 0; i < 8; i++)
                    o[i] += __shfl_xor_sync(0xffffffffu, o[i], s);
            }
            if (lane < 4) {
                float* p = &g_pool[n * 64 + half * 32 + q * 8];
                ((float4*)p)[0] = make_float4(o[0], o[1], o[2], o[3]);
                ((float4*)p)[1] = make_float4(o[4], o[5], o[6], o[7]);
            }
        }
    }
}

// Reduce the 2 per-half partials into the final [NSUM, 32] output.
__global__ void k_pool_reduce(float* __restrict__ dout) {
    int i = blockIdx.x * blockDim.x + threadIdx.x;   // i = n*32 + c
    if (i < NSUM * 32) {
        int n = i >> 5, c = i & 31;
        dout[i] = g_pool[n * 64 + c] + g_pool[n * 64 + 32 + c];
    }
}

// ---------------------------------------------------------------------------
extern "C" void kernel_launch(void* const* d_in, const int* in_sizes, int n_in,
                              void* d_out, int out_size)
{
    const float* W    = (const float*)d_in[0];   // [6400, 64, 16]
    const int*   ei   = (const int*)d_in[1];     // [2, E] row-major
    const float* eps  = (const float*)d_in[2];   // [3]
    const float* W1_0 = (const float*)d_in[3];
    const float* b1_0 = (const float*)d_in[4];
    const float* W2_0 = (const float*)d_in[5];
    const float* b2_0 = (const float*)d_in[6];
    const float* W1_1 = (const float*)d_in[7];
    const float* b1_1 = (const float*)d_in[8];
    const float* W2_1 = (const float*)d_in[9];
    const float* b2_1 = (const float*)d_in[10];
    const float* W1_2 = (const float*)d_in[11];
    const float* b1_2 = (const float*)d_in[12];
    const float* W2_2 = (const float*)d_in[13];
    const float* b2_2 = (const float*)d_in[14];
    float* out = (float*)d_out;

    const int* src = ei;
    const int* dst = ei + EDGES;

    // CSR build (g_cnt is zero at load and re-zeroed by k_scan each call)
    k_count<<<(EDGES + 255) / 256, 256>>>(dst);          // launch 0
    k_scan<<<1, 1024>>>();                                // launch 1
    k_scatter<<<(EDGES + 255) / 256, 256>>>(src, dst);   // launch 2

    const int GRID = 296;   // one persistent wave: 2 blocks x 148 SMs

    // Layer 0: input W (D=16) -> g_h[0]  (relu after MLP)   -- launch 3
    k_layer<16, true, false><<<GRID, 256>>>(W, 0, 0, eps, 0,
                                            W1_0, b1_0, W2_0, b2_0);
    // Layer 1: g_h[0] -> g_h[1]  (relu after MLP)           -- launch 4
    k_layer<32, true, false><<<GRID, 256>>>(nullptr, 0, 1, eps, 1,
                                            W1_1, b1_1, W2_1, b2_1);
    // Layer 2: g_h[1] -> per-half pool partials (no relu)   -- launch 5
    k_layer<32, false, true><<<GRID, 256>>>(nullptr, 1, 0, eps, 2,
                                            W1_2, b1_2, W2_2, b2_2);
    // Final: reduce 2 half partials per node                -- launch 6
    k_pool_reduce<<<(NSUM * 32 + 255) / 256, 256>>>(out);
}

// round 6
// speedup vs baseline: 1.8557x; 1.0121x over previous
#include <cuda_runtime.h>

// Problem constants (fixed shapes per reference)
#define NSUM 6400
#define NMAX 64
#define MDIM 16
#define HDIM 32
#define ODIM 32
#define EDGES 51200

// Scratch: ping/pong node-feature buffers + CSR structures + pool partials.
__device__ float g_h[2][NSUM * NMAX * HDIM];   // 2 x 52.4 MB
__device__ float g_pool[NSUM * 2 * 32];        // per-half pool partials
__device__ int g_cnt[NSUM];                    // zero-init at load; k_scan re-zeroes
__device__ int g_off[NSUM + 1];
__device__ int g_cur[NSUM];
__device__ int g_esrc[EDGES];

// ---------------------------------------------------------------------------
// CSR build: count -> scan (self-cleaning) -> scatter
// ---------------------------------------------------------------------------
__global__ void k_count(const int* __restrict__ dst) {
    int e = blockIdx.x * blockDim.x + threadIdx.x;
    if (e < EDGES) atomicAdd(&g_cnt[dst[e]], 1);
}

__global__ void k_scan() {
    __shared__ int part[1024];
    int tid = threadIdx.x;
    const int CH = (NSUM + 1023) / 1024;  // 7
    int base = tid * CH;
    int s = 0;
    #pragma unroll
    for (int i = 0; i < CH; i++) {
        int idx = base + i;
        if (idx < NSUM) s += g_cnt[idx];
    }
    part[tid] = s;
    __syncthreads();
    int own = s;
    for (int d = 1; d < 1024; d <<= 1) {
        int v = (tid >= d) ? part[tid - d] : 0;
        __syncthreads();
        part[tid] += v;
        __syncthreads();
    }
    int run = part[tid] - own;
    #pragma unroll
    for (int i = 0; i < CH; i++) {
        int idx = base + i;
        if (idx < NSUM) {
            g_off[idx] = run;
            g_cur[idx] = run;
            run += g_cnt[idx];
            g_cnt[idx] = 0;          // self-clean for the next replay
        }
    }
    if (tid == 1023) g_off[NSUM] = EDGES;
}

__global__ void k_scatter(const int* __restrict__ src, const int* __restrict__ dst) {
    int e = blockIdx.x * blockDim.x + threadIdx.x;
    if (e < EDGES) {
        int p = atomicAdd(&g_cur[dst[e]], 1);
        g_esrc[p] = src[e];
    }
}

// ---------------------------------------------------------------------------
// Warp-autonomous fused GIN layer, vectorized-LDS mapping.
// Unit = (node, half of 32 rows). One warp per unit; grid-stride over units.
// Lane (lr = lane>>2, q = lane&3) owns 4 rows {lr, lr+8, lr+16, lr+24} of
// its half, and 8 output columns [q*8, q*8+8).
//   gather : edge ids broadcast via shfl; 2-edge-wide register-buffered loads
//   MLP    : ALL smem access as LDS.128 with broadcast dedup —
//            x/hid read one float4 per row per 4-step block (1 wavefront),
//            weights read two float4 per step (1 wavefront each).
//   pool   : local 4-row sum + shfl over lr bits; 2 partials/node + reduce
// ---------------------------------------------------------------------------
template <int DIN, bool RELU_OUT, bool POOL>
__global__ __launch_bounds__(256, 2) void k_layer(
    const float* __restrict__ ext_in, int in_buf, int out_buf,
    const float* __restrict__ epsv, int layer,
    const float* __restrict__ W1, const float* __restrict__ b1,
    const float* __restrict__ W2, const float* __restrict__ b2)
{
    constexpr int R4   = DIN / 4;          // float4 per row
    constexpr int PFR  = R4 / 4;           // float4 per lane per row (1 or 2)
    constexpr int S    = 4 * PFR;          // float4 slots per lane (4 or 8)
    constexpr int V4   = NMAX * R4;        // float4 per node block
    constexpr int PAD  = 36;               // row stride (floats); 144B = 16B-aligned

    __shared__ float sW1[DIN * 32];
    __shared__ float sW2[32 * 32];
    __shared__ float sb1[32], sb2[32];
    __shared__ float sxh[8][32 * PAD];     // per-warp x/hid union slices

    int tid = threadIdx.x;
    int wid = tid >> 5, lane = tid & 31;
    int lr = lane >> 2, q = lane & 3;

    for (int i = tid; i < DIN * 32; i += 256) sW1[i] = W1[i];
    for (int i = tid; i < 32 * 32;  i += 256) sW2[i] = W2[i];
    if (tid < 32) { sb1[tid] = b1[tid]; sb2[tid] = b2[tid]; }
    float ep1 = 1.0f + epsv[layer];
    __syncthreads();

    const float*  h_in = ext_in ? ext_in : g_h[in_buf];
    const float4* h4   = (const float4*)h_in;
    float* sxw = sxh[wid];

    for (int unit = blockIdx.x * 8 + wid; unit < NSUM * 2; unit += gridDim.x * 8) {
        int n = unit >> 1, half = unit & 1;
        // lane's float4 slots within the node block (4 rows x PFR slices)
        int slot[S];
        #pragma unroll
        for (int m = 0; m < 4; m++)
            #pragma unroll
            for (int v = 0; v < PFR; v++)
                slot[m * PFR + v] = (half * 32 + lr + 8 * m) * R4 + q + 4 * v;

        // ---- gather: acc = (1+eps)*h[n] + sum_neighbors h[src] ----
        float4 acc[S];
        {
            const float4* hn = h4 + (size_t)n * V4;
            #pragma unroll
            for (int s = 0; s < S; s++) {
                float4 t = hn[slot[s]];
                acc[s] = make_float4(ep1 * t.x, ep1 * t.y, ep1 * t.z, ep1 * t.w);
            }
        }
        int e0 = g_off[n], e1 = g_off[n + 1];
        for (int base = e0; base < e1; base += 32) {
            int cnt = min(32, e1 - base);
            int id = (lane < cnt) ? g_esrc[base + lane] : 0;
            int e = 0;
            for (; e + 2 <= cnt; e += 2) {
                int sa = __shfl_sync(0xffffffffu, id, e);
                int sb = __shfl_sync(0xffffffffu, id, e + 1);
                const float4* pa = h4 + (size_t)sa * V4;
                const float4* pb = h4 + (size_t)sb * V4;
                float4 ta[S], tb[S];
                #pragma unroll
                for (int s = 0; s < S; s++) ta[s] = pa[slot[s]];
                #pragma unroll
                for (int s = 0; s < S; s++) tb[s] = pb[slot[s]];
                #pragma unroll
                for (int s = 0; s < S; s++) {
                    acc[s].x += ta[s].x; acc[s].y += ta[s].y;
                    acc[s].z += ta[s].z; acc[s].w += ta[s].w;
                }
                #pragma unroll
                for (int s = 0; s < S; s++) {
                    acc[s].x += tb[s].x; acc[s].y += tb[s].y;
                    acc[s].z += tb[s].z; acc[s].w += tb[s].w;
                }
            }
            if (e < cnt) {
                int sa = __shfl_sync(0xffffffffu, id, e);
                const float4* pa = h4 + (size_t)sa * V4;
                #pragma unroll
                for (int s = 0; s < S; s++) {
                    float4 t = pa[slot[s]];
                    acc[s].x += t.x; acc[s].y += t.y;
                    acc[s].z += t.z; acc[s].w += t.w;
                }
            }
        }
        // stage x into this warp's smem slice (local rows lr+8m)
        #pragma unroll
        for (int m = 0; m < 4; m++)
            #pragma unroll
            for (int v = 0; v < PFR; v++) {
                float* p = &sxw[(lr + 8 * m) * PAD + 4 * q + 16 * v];
                *(float4*)p = acc[m * PFR + v];
            }
        __syncwarp();

        // ---- hidden: hid = relu(x @ W1 + b1); lane: 4 rows x 8 cols ----
        float hacc[32];
        #pragma unroll
        for (int m = 0; m < 4; m++)
            #pragma unroll
            for (int i = 0; i < 8; i++) hacc[m * 8 + i] = sb1[q * 8 + i];
        #pragma unroll
        for (int kb = 0; kb < DIN / 4; kb++) {
            // one LDS.128 per row: 8 distinct rows x 16B = 1 wavefront
            float4 xq0 = *(const float4*)&sxw[(lr +  0) * PAD + kb * 4];
            float4 xq1 = *(const float4*)&sxw[(lr +  8) * PAD + kb * 4];
            float4 xq2 = *(const float4*)&sxw[(lr + 16) * PAD + kb * 4];
            float4 xq3 = *(const float4*)&sxw[(lr + 24) * PAD + kb * 4];
            float x0[4] = {xq0.x, xq0.y, xq0.z, xq0.w};
            float x1[4] = {xq1.x, xq1.y, xq1.z, xq1.w};
            float x2[4] = {xq2.x, xq2.y, xq2.z, xq2.w};
            float x3[4] = {xq3.x, xq3.y, xq3.z, xq3.w};
            #pragma unroll
            for (int kk = 0; kk < 4; kk++) {
                int k = kb * 4 + kk;
                float4 w0 = *(const float4*)&sW1[k * 32 + q * 8];
                float4 w1 = *(const float4*)&sW1[k * 32 + q * 8 + 4];
                float w[8] = {w0.x, w0.y, w0.z, w0.w, w1.x, w1.y, w1.z, w1.w};
                #pragma unroll
                for (int i = 0; i < 8; i++) {
                    hacc[ 0 + i] = fmaf(x0[kk], w[i], hacc[ 0 + i]);
                    hacc[ 8 + i] = fmaf(x1[kk], w[i], hacc[ 8 + i]);
                    hacc[16 + i] = fmaf(x2[kk], w[i], hacc[16 + i]);
                    hacc[24 + i] = fmaf(x3[kk], w[i], hacc[24 + i]);
                }
            }
        }
        __syncwarp();   // all x reads done before hid overwrites the buffer
        #pragma unroll
        for (int m = 0; m < 4; m++) {
            float* p = &sxw[(lr + 8 * m) * PAD + q * 8];
            ((float4*)p)[0] = make_float4(fmaxf(hacc[m*8+0], 0.f), fmaxf(hacc[m*8+1], 0.f),
                                          fmaxf(hacc[m*8+2], 0.f), fmaxf(hacc[m*8+3], 0.f));
            ((float4*)p)[1] = make_float4(fmaxf(hacc[m*8+4], 0.f), fmaxf(hacc[m*8+5], 0.f),
                                          fmaxf(hacc[m*8+6], 0.f), fmaxf(hacc[m*8+7], 0.f));
        }
        __syncwarp();

        // ---- output: out = hid @ W2 + b2 ----
        float oacc[32];
        #pragma unroll
        for (int m = 0; m < 4; m++)
            #pragma unroll
            for (int i = 0; i < 8; i++) oacc[m * 8 + i] = sb2[q * 8 + i];
        #pragma unroll
        for (int jb = 0; jb < 8; jb++) {
            float4 hq0 = *(const float4*)&sxw[(lr +  0) * PAD + jb * 4];
            float4 hq1 = *(const float4*)&sxw[(lr +  8) * PAD + jb * 4];
            float4 hq2 = *(const float4*)&sxw[(lr + 16) * PAD + jb * 4];
            float4 hq3 = *(const float4*)&sxw[(lr + 24) * PAD + jb * 4];
            float h0[4] = {hq0.x, hq0.y, hq0.z, hq0.w};
            float h1[4] = {hq1.x, hq1.y, hq1.z, hq1.w};
            float h2[4] = {hq2.x, hq2.y, hq2.z, hq2.w};
            float h3[4] = {hq3.x, hq3.y, hq3.z, hq3.w};
            #pragma unroll
            for (int jj = 0; jj < 4; jj++) {
                int j = jb * 4 + jj;
                float4 w0 = *(const float4*)&sW2[j * 32 + q * 8];
                float4 w1 = *(const float4*)&sW2[j * 32 + q * 8 + 4];
                float w[8] = {w0.x, w0.y, w0.z, w0.w, w1.x, w1.y, w1.z, w1.w};
                #pragma unroll
                for (int i = 0; i < 8; i++) {
                    oacc[ 0 + i] = fmaf(h0[jj], w[i], oacc[ 0 + i]);
                    oacc[ 8 + i] = fmaf(h1[jj], w[i], oacc[ 8 + i]);
                    oacc[16 + i] = fmaf(h2[jj], w[i], oacc[16 + i]);
                    oacc[24 + i] = fmaf(h3[jj], w[i], oacc[24 + i]);
                }
            }
        }
        __syncwarp();   // hid reads done before next iteration stages x

        if (!POOL) {
            #pragma unroll
            for (int m = 0; m < 4; m++) {
                int grow = half * 32 + lr + 8 * m;
                float* out = g_h[out_buf] + (size_t)n * (NMAX * 32) + grow * 32 + q * 8;
                float4 o0 = make_float4(oacc[m*8+0], oacc[m*8+1], oacc[m*8+2], oacc[m*8+3]);
                float4 o1 = make_float4(oacc[m*8+4], oacc[m*8+5], oacc[m*8+6], oacc[m*8+7]);
                if (RELU_OUT) {
                    o0.x = fmaxf(o0.x, 0.f); o0.y = fmaxf(o0.y, 0.f);
                    o0.z = fmaxf(o0.z, 0.f); o0.w = fmaxf(o0.w, 0.f);
                    o1.x = fmaxf(o1.x, 0.f); o1.y = fmaxf(o1.y, 0.f);
                    o1.z = fmaxf(o1.z, 0.f); o1.w = fmaxf(o1.w, 0.f);
                }
                ((float4*)out)[0] = o0;
                ((float4*)out)[1] = o1;
            }
        } else {
            // local sum over this lane's 4 rows
            float o[8];
            #pragma unroll
            for (int i = 0; i < 8; i++)
                o[i] = oacc[i] + oacc[8 + i] + oacc[16 + i] + oacc[24 + i];
            // reduce over lr (lane bits 2..4)
            #pragma unroll
            for (int s = 4; s <= 16; s <<= 1) {
                #pragma unroll
                for (int i = 0; i < 8; i++)
                    o[i] += __shfl_xor_sync(0xffffffffu, o[i], s);
            }
            if (lane < 4) {
                float* p = &g_pool[n * 64 + half * 32 + q * 8];
                ((float4*)p)[0] = make_float4(o[0], o[1], o[2], o[3]);
                ((float4*)p)[1] = make_float4(o[4], o[5], o[6], o[7]);
            }
        }
    }
}

// Reduce the 2 per-half partials into the final [NSUM, 32] output.
__global__ void k_pool_reduce(float* __restrict__ dout) {
    int i = blockIdx.x * blockDim.x + threadIdx.x;   // i = n*32 + c
    if (i < NSUM * 32) {
        int n = i >> 5, c = i & 31;
        dout[i] = g_pool[n * 64 + c] + g_pool[n * 64 + 32 + c];
    }
}

// ---------------------------------------------------------------------------
extern "C" void kernel_launch(void* const* d_in, const int* in_sizes, int n_in,
                              void* d_out, int out_size)
{
    const float* W    = (const float*)d_in[0];   // [6400, 64, 16]
    const int*   ei   = (const int*)d_in[1];     // [2, E] row-major
    const float* eps  = (const float*)d_in[2];   // [3]
    const float* W1_0 = (const float*)d_in[3];
    const float* b1_0 = (const float*)d_in[4];
    const float* W2_0 = (const float*)d_in[5];
    const float* b2_0 = (const float*)d_in[6];
    const float* W1_1 = (const float*)d_in[7];
    const float* b1_1 = (const float*)d_in[8];
    const float* W2_1 = (const float*)d_in[9];
    const float* b2_1 = (const float*)d_in[10];
    const float* W1_2 = (const float*)d_in[11];
    const float* b1_2 = (const float*)d_in[12];
    const float* W2_2 = (const float*)d_in[13];
    const float* b2_2 = (const float*)d_in[14];
    float* out = (float*)d_out;

    const int* src = ei;
    const int* dst = ei + EDGES;

    // CSR build (g_cnt is zero at load and re-zeroed by k_scan each call)
    k_count<<<(EDGES + 255) / 256, 256>>>(dst);          // launch 0
    k_scan<<<1, 1024>>>();                                // launch 1
    k_scatter<<<(EDGES + 255) / 256, 256>>>(src, dst);   // launch 2

    const int GRID = 296;   // one persistent wave: 2 blocks x 148 SMs

    // Layer 0: input W (D=16) -> g_h[0]  (relu after MLP)   -- launch 3
    k_layer<16, true, false><<<GRID, 256>>>(W, 0, 0, eps, 0,
                                            W1_0, b1_0, W2_0, b2_0);
    // Layer 1: g_h[0] -> g_h[1]  (relu after MLP)           -- launch 4
    k_layer<32, true, false><<<GRID, 256>>>(nullptr, 0, 1, eps, 1,
                                            W1_1, b1_1, W2_1, b2_1);
    // Layer 2: g_h[1] -> per-half pool partials (no relu)   -- launch 5
    k_layer<32, false, true><<<GRID, 256>>>(nullptr, 1, 0, eps, 2,
                                            W1_2, b1_2, W2_2, b2_2);
    // Final: reduce 2 half partials per node                -- launch 6
    k_pool_reduce<<<(NSUM * 32 + 255) / 256, 256>>>(out);
}